// round 6
// baseline (speedup 1.0000x reference)
#include <cuda_runtime.h>
#include <math.h>

// Problem shape (fixed by reference): X (64,4096), F (64,64), Q_S (4096,4096),
// Lambda_S (4096,), gamma scalar. Output Z (64,4096) fp32.
#define M64 64
#define NN 4096
#define KK 4096
#define NT 64          // GEMM N-tile
#define BK 16          // GEMM K-tile
#define KSPLIT 8       // split-K factor -> 64*8 = 512 CTAs per big GEMM
#define KC (KK / KSPLIT)
#define WSZ (M64 * NN) // 262144
#define NSTEPS 5       // doubling steps -> 32 Neumann terms

// Scratch (static device globals; no allocations anywhere).
__device__ float g_Gpow[NSTEPS * M64 * M64]; // G^(2^t), t = 0..4
__device__ float g_part[KSPLIT * WSZ];       // split-K partials (8 MB)
__device__ float g_W[2 * WSZ];               // ping-pong W buffers

// ---------------------------------------------------------------------------
// Kernel A: G = F^T F / (||F^T F||_F + 1e-12), then powers G^2, G^4, G^8, G^16
// by repeated squaring (G stays symmetric, so row-row smem access is valid).
// Single CTA, 256 threads, each owns a 4x4 tile of the 64x64 matrices.
// ---------------------------------------------------------------------------
__global__ void prep_gpow_kernel(const float* __restrict__ F) {
    __shared__ float Fs[M64][M64 + 4];
    __shared__ float Gs[M64][M64 + 4];
    __shared__ float rbuf[8];
    __shared__ float sh_scale;

    const int tid = threadIdx.x;           // 256 threads
    const int lane = tid & 31, wid = tid >> 5;

    // Load F (row-major 64x64) into smem, vectorized.
    #pragma unroll
    for (int l = 0; l < 4; l++) {
        int idx = tid + l * 256;
        int i = idx >> 4, kq = idx & 15;
        *(float4*)&Fs[i][kq * 4] = *(const float4*)&F[i * 64 + kq * 4];
    }
    __syncthreads();

    const int ti = (tid >> 4) * 4;  // output rows ti..ti+3
    const int tj = (tid & 15) * 4;  // output cols tj..tj+3

    // FF[i][j] = sum_k F[k][i] * F[k][j]  (both row-contiguous reads)
    float acc[4][4];
    #pragma unroll
    for (int r = 0; r < 4; r++)
        #pragma unroll
        for (int c = 0; c < 4; c++) acc[r][c] = 0.0f;

    for (int k = 0; k < 64; k++) {
        float4 a = *(float4*)&Fs[k][ti];
        float4 b = *(float4*)&Fs[k][tj];
        float av[4] = {a.x, a.y, a.z, a.w};
        float bv[4] = {b.x, b.y, b.z, b.w};
        #pragma unroll
        for (int r = 0; r < 4; r++)
            #pragma unroll
            for (int c = 0; c < 4; c++) acc[r][c] += av[r] * bv[c];
    }

    // Frobenius norm of FF via block reduction.
    float ss = 0.0f;
    #pragma unroll
    for (int r = 0; r < 4; r++)
        #pragma unroll
        for (int c = 0; c < 4; c++) ss += acc[r][c] * acc[r][c];
    #pragma unroll
    for (int off = 16; off > 0; off >>= 1)
        ss += __shfl_xor_sync(0xffffffffu, ss, off);
    if (lane == 0) rbuf[wid] = ss;
    __syncthreads();
    if (tid == 0) {
        float tot = 0.0f;
        #pragma unroll
        for (int w = 0; w < 8; w++) tot += rbuf[w];
        sh_scale = 1.0f / (sqrtf(tot) + 1e-12f);
    }
    __syncthreads();
    const float scale = sh_scale;

    // G = FF * scale  -> smem + g_Gpow[0]
    #pragma unroll
    for (int r = 0; r < 4; r++)
        #pragma unroll
        for (int c = 0; c < 4; c++) {
            float v = acc[r][c] * scale;
            Gs[ti + r][tj + c] = v;
            g_Gpow[(ti + r) * 64 + (tj + c)] = v;
        }
    __syncthreads();

    // Repeated squaring: G^(2^t) = (G^(2^(t-1)))^2.
    for (int t = 1; t < NSTEPS; t++) {
        float a2[4][4];
        #pragma unroll
        for (int r = 0; r < 4; r++)
            #pragma unroll
            for (int c = 0; c < 4; c++) a2[r][c] = 0.0f;

        for (int k = 0; k < 64; k++) {
            // out[i][j] = sum_k Gs[k][i]*Gs[k][j]  (valid: Gs symmetric)
            float4 a = *(float4*)&Gs[k][ti];
            float4 b = *(float4*)&Gs[k][tj];
            float av[4] = {a.x, a.y, a.z, a.w};
            float bv[4] = {b.x, b.y, b.z, b.w};
            #pragma unroll
            for (int r = 0; r < 4; r++)
                #pragma unroll
                for (int c = 0; c < 4; c++) a2[r][c] += av[r] * bv[c];
        }
        __syncthreads();
        #pragma unroll
        for (int r = 0; r < 4; r++)
            #pragma unroll
            for (int c = 0; c < 4; c++) {
                Gs[ti + r][tj + c] = a2[r][c];
                g_Gpow[t * 4096 + (ti + r) * 64 + (tj + c)] = a2[r][c];
            }
        __syncthreads();
    }
}

// ---------------------------------------------------------------------------
// Split-K GEMM: C(64 x 4096) = A(64 x 4096) * B, partials into g_part.
//   MODE 0: B accessed as Q_S[k][j]   (Y = X @ Q_S)
//   MODE 1: B accessed as Q_S[j][k]   (Z = W @ Q_S^T), A comes from g_W buf 1
// 128 threads/CTA, each computes an 8(M) x 4(N) register tile. Grid (64, 8).
// ---------------------------------------------------------------------------
template <int MODE>
__global__ void gemm64_kernel(const float* __restrict__ A,
                              const float* __restrict__ B) {
    __shared__ float As[BK][M64 + 4];  // [k][i]
    __shared__ float Bs[BK][NT + 4];   // [k][j]

    const int j0 = blockIdx.x * NT;
    const int k0 = blockIdx.y * KC;
    const int tid = threadIdx.x;       // 128
    const int tx = tid & 15;           // col group -> 4 cols
    const int ty = tid >> 4;           // row group -> 8 rows (0..7)

    const float* Ap = (MODE == 0) ? A : (g_W + WSZ);

    float acc[8][4];
    #pragma unroll
    for (int r = 0; r < 8; r++)
        #pragma unroll
        for (int c = 0; c < 4; c++) acc[r][c] = 0.0f;

    for (int kk = 0; kk < KC; kk += BK) {
        // A tile: 64 x 16 -> As[k][i]
        #pragma unroll
        for (int l = 0; l < 8; l++) {
            int idx = tid + l * 128;
            int i = idx >> 4, k = idx & 15;
            As[k][i] = Ap[i * KK + k0 + kk + k];
        }
        // B tile: 16 x 64 -> Bs[k][j]
        #pragma unroll
        for (int l = 0; l < 8; l++) {
            int idx = tid + l * 128;
            if (MODE == 0) {
                int k = idx >> 6, j = idx & 63;
                Bs[k][j] = B[(size_t)(k0 + kk + k) * NN + j0 + j];
            } else {
                int j = idx >> 4, k = idx & 15;
                Bs[k][j] = B[(size_t)(j0 + j) * KK + k0 + kk + k];
            }
        }
        __syncthreads();

        #pragma unroll
        for (int k = 0; k < BK; k++) {
            float4 a0 = *(float4*)&As[k][ty * 8];
            float4 a1 = *(float4*)&As[k][ty * 8 + 4];
            float4 b  = *(float4*)&Bs[k][tx * 4];
            float av[8] = {a0.x, a0.y, a0.z, a0.w, a1.x, a1.y, a1.z, a1.w};
            float bv[4] = {b.x, b.y, b.z, b.w};
            #pragma unroll
            for (int r = 0; r < 8; r++)
                #pragma unroll
                for (int c = 0; c < 4; c++) acc[r][c] += av[r] * bv[c];
        }
        __syncthreads();
    }

    float* out = g_part + (size_t)blockIdx.y * WSZ;
    #pragma unroll
    for (int r = 0; r < 8; r++) {
        int i = ty * 8 + r;
        float4 v = make_float4(acc[r][0], acc[r][1], acc[r][2], acc[r][3]);
        *(float4*)&out[i * NN + j0 + tx * 4] = v;
    }
}

// ---------------------------------------------------------------------------
// Sum the 8 split-K partials. Writes g_W[0] (use_dout=0) or d_out (use_dout=1).
// ---------------------------------------------------------------------------
__global__ void reduce_kernel(float* __restrict__ dout, int use_dout) {
    int idx = blockIdx.x * blockDim.x + threadIdx.x;  // float4 index, 65536 total
    float4 s = make_float4(0.f, 0.f, 0.f, 0.f);
    #pragma unroll
    for (int p = 0; p < KSPLIT; p++) {
        float4 v = *(const float4*)&g_part[(size_t)p * WSZ + idx * 4];
        s.x += v.x; s.y += v.y; s.z += v.z; s.w += v.w;
    }
    float* out = use_dout ? dout : g_W;
    *(float4*)&out[idx * 4] = s;
}

// ---------------------------------------------------------------------------
// Doubling step t: Wout = Win + diag-col(c_j^(2^t)) * (G^(2^t) @ Win)
// c_j = gamma * Lambda_S[j]. After t = 0..4 this equals sum_{k<32} c^k G^k Y,
// i.e. (I - c_j G)^{-1} y_j to ~1e-18 (spectral radius <= 0.76 * lam_max(G)).
// Grid: 128 CTAs x 32 columns, 256 threads, 4(M) x 2(N) tiles.
// ---------------------------------------------------------------------------
__global__ void solve_step_kernel(const float* __restrict__ Lam,
                                  const float* __restrict__ gamma,
                                  int t) {
    __shared__ float Gs[M64][M64 + 4];
    __shared__ float Ws[M64][32 + 4];

    const float* Win  = g_W + (size_t)(t & 1) * WSZ;
    float*       Wout = g_W + (size_t)((t + 1) & 1) * WSZ;
    const float* Gp   = g_Gpow + (size_t)t * M64 * M64;

    const int j0 = blockIdx.x * 32;
    const int tid = threadIdx.x;  // 256

    #pragma unroll
    for (int l = 0; l < 4; l++) {
        int idx = tid + l * 256;
        int i = idx >> 4, kq = idx & 15;
        *(float4*)&Gs[i][kq * 4] = *(const float4*)&Gp[i * 64 + kq * 4];
    }
    #pragma unroll
    for (int l = 0; l < 8; l++) {
        int idx = tid + l * 256;
        int k = idx >> 5, c = idx & 31;
        Ws[k][c] = Win[k * NN + j0 + c];
    }
    __syncthreads();

    const int ty = tid >> 4;  // rows ty*4 .. +3
    const int tx = tid & 15;  // cols tx*2, tx*2+1

    float acc[4][2];
    #pragma unroll
    for (int r = 0; r < 4; r++) { acc[r][0] = 0.f; acc[r][1] = 0.f; }

    for (int k = 0; k < 64; k++) {
        // (G W)[i][j] = sum_k G[i][k] W[k][j]; Gs[k][i] == G[i][k] (symmetric)
        float4 a = *(float4*)&Gs[k][ty * 4];
        float b0 = Ws[k][tx * 2];
        float b1 = Ws[k][tx * 2 + 1];
        acc[0][0] += a.x * b0;  acc[0][1] += a.x * b1;
        acc[1][0] += a.y * b0;  acc[1][1] += a.y * b1;
        acc[2][0] += a.z * b0;  acc[2][1] += a.z * b1;
        acc[3][0] += a.w * b0;  acc[3][1] += a.w * b1;
    }

    const float gm = gamma[0];
    #pragma unroll
    for (int c = 0; c < 2; c++) {
        int j = j0 + tx * 2 + c;
        float cv = gm * Lam[j];
        float p = cv;
        for (int s = 0; s < t; s++) p *= p;   // p = cv^(2^t)
        #pragma unroll
        for (int r = 0; r < 4; r++) {
            int i = ty * 4 + r;
            Wout[i * NN + j] = Ws[i][tx * 2 + c] + p * acc[r][c];
        }
    }
}

// ---------------------------------------------------------------------------
extern "C" void kernel_launch(void* const* d_in, const int* in_sizes, int n_in,
                              void* d_out, int out_size) {
    const float* X   = (const float*)d_in[0];  // 64 x 4096
    const float* F   = (const float*)d_in[1];  // 64 x 64
    const float* Q   = (const float*)d_in[2];  // 4096 x 4096
    const float* Lam = (const float*)d_in[3];  // 4096
    const float* gam = (const float*)d_in[4];  // scalar
    float* out = (float*)d_out;                // 64 x 4096

    // G and its 2^t powers (independent small chain).
    prep_gpow_kernel<<<1, 256>>>(F);

    // Y = X @ Q_S  (split-K partials, then reduce into g_W[0]).
    gemm64_kernel<0><<<dim3(NN / NT, KSPLIT), 128>>>(X, Q);
    reduce_kernel<<<(WSZ / 4) / 256, 256>>>(nullptr, 0);

    // W = (I - c_j G)^{-1} Y  columnwise via 5 geometric-doubling steps.
    for (int t = 0; t < NSTEPS; t++)
        solve_step_kernel<<<NN / 32, 256>>>(Lam, gam, t);

    // Z = W @ Q_S^T  (W ends in g_W buffer 1), reduce straight into d_out.
    gemm64_kernel<1><<<dim3(NN / NT, KSPLIT), 128>>>(nullptr, Q);
    reduce_kernel<<<(WSZ / 4) / 256, 256>>>(out, 1);
}

// round 10
// speedup vs baseline: 1.0007x; 1.0007x over previous
#include <cuda_runtime.h>
#include <math.h>

// Problem shape (fixed by reference): X (64,4096), F (64,64), Q_S (4096,4096),
// Lambda_S (4096,), gamma scalar. Output Z (64,4096) fp32.
#define M64 64
#define NN 4096
#define KK 4096
#define NT 64          // GEMM N-tile
#define BK 16          // GEMM K-tile
#define KSPLIT 8       // split-K factor -> 64*8 = 512 CTAs per big GEMM
#define KC (KK / KSPLIT)
#define WSZ (M64 * NN) // 262144
#define NSTEPS 5       // doubling steps -> 32 Neumann terms

// Scratch (static device globals; no allocations anywhere).
__device__ float g_Gpow[NSTEPS * M64 * M64]; // G^(2^t), t = 0..4
__device__ float g_part[KSPLIT * WSZ];       // split-K partials (8 MB)
__device__ float g_W[2 * WSZ];               // ping-pong W buffers

// ---------------------------------------------------------------------------
// Kernel A: G = F^T F / (||F^T F||_F + 1e-12), then powers G^2, G^4, G^8, G^16
// by repeated squaring (G stays symmetric, so row-row smem access is valid).
// Single CTA, 256 threads, each owns a 4x4 tile of the 64x64 matrices.
// ---------------------------------------------------------------------------
__global__ void prep_gpow_kernel(const float* __restrict__ F) {
    __shared__ float Fs[M64][M64 + 4];
    __shared__ float Gs[M64][M64 + 4];
    __shared__ float rbuf[8];
    __shared__ float sh_scale;

    const int tid = threadIdx.x;           // 256 threads
    const int lane = tid & 31, wid = tid >> 5;

    // Load F (row-major 64x64) into smem, vectorized.
    #pragma unroll
    for (int l = 0; l < 4; l++) {
        int idx = tid + l * 256;
        int i = idx >> 4, kq = idx & 15;
        *(float4*)&Fs[i][kq * 4] = *(const float4*)&F[i * 64 + kq * 4];
    }
    __syncthreads();

    const int ti = (tid >> 4) * 4;  // output rows ti..ti+3
    const int tj = (tid & 15) * 4;  // output cols tj..tj+3

    // FF[i][j] = sum_k F[k][i] * F[k][j]  (both row-contiguous reads)
    float acc[4][4];
    #pragma unroll
    for (int r = 0; r < 4; r++)
        #pragma unroll
        for (int c = 0; c < 4; c++) acc[r][c] = 0.0f;

    for (int k = 0; k < 64; k++) {
        float4 a = *(float4*)&Fs[k][ti];
        float4 b = *(float4*)&Fs[k][tj];
        float av[4] = {a.x, a.y, a.z, a.w};
        float bv[4] = {b.x, b.y, b.z, b.w};
        #pragma unroll
        for (int r = 0; r < 4; r++)
            #pragma unroll
            for (int c = 0; c < 4; c++) acc[r][c] += av[r] * bv[c];
    }

    // Frobenius norm of FF via block reduction.
    float ss = 0.0f;
    #pragma unroll
    for (int r = 0; r < 4; r++)
        #pragma unroll
        for (int c = 0; c < 4; c++) ss += acc[r][c] * acc[r][c];
    #pragma unroll
    for (int off = 16; off > 0; off >>= 1)
        ss += __shfl_xor_sync(0xffffffffu, ss, off);
    if (lane == 0) rbuf[wid] = ss;
    __syncthreads();
    if (tid == 0) {
        float tot = 0.0f;
        #pragma unroll
        for (int w = 0; w < 8; w++) tot += rbuf[w];
        sh_scale = 1.0f / (sqrtf(tot) + 1e-12f);
    }
    __syncthreads();
    const float scale = sh_scale;

    // G = FF * scale  -> smem + g_Gpow[0]
    #pragma unroll
    for (int r = 0; r < 4; r++)
        #pragma unroll
        for (int c = 0; c < 4; c++) {
            float v = acc[r][c] * scale;
            Gs[ti + r][tj + c] = v;
            g_Gpow[(ti + r) * 64 + (tj + c)] = v;
        }
    __syncthreads();

    // Repeated squaring: G^(2^t) = (G^(2^(t-1)))^2.
    for (int t = 1; t < NSTEPS; t++) {
        float a2[4][4];
        #pragma unroll
        for (int r = 0; r < 4; r++)
            #pragma unroll
            for (int c = 0; c < 4; c++) a2[r][c] = 0.0f;

        for (int k = 0; k < 64; k++) {
            // out[i][j] = sum_k Gs[k][i]*Gs[k][j]  (valid: Gs symmetric)
            float4 a = *(float4*)&Gs[k][ti];
            float4 b = *(float4*)&Gs[k][tj];
            float av[4] = {a.x, a.y, a.z, a.w};
            float bv[4] = {b.x, b.y, b.z, b.w};
            #pragma unroll
            for (int r = 0; r < 4; r++)
                #pragma unroll
                for (int c = 0; c < 4; c++) a2[r][c] += av[r] * bv[c];
        }
        __syncthreads();
        #pragma unroll
        for (int r = 0; r < 4; r++)
            #pragma unroll
            for (int c = 0; c < 4; c++) {
                Gs[ti + r][tj + c] = a2[r][c];
                g_Gpow[t * 4096 + (ti + r) * 64 + (tj + c)] = a2[r][c];
            }
        __syncthreads();
    }
}

// ---------------------------------------------------------------------------
// Split-K GEMM: C(64 x 4096) = A(64 x 4096) * B, partials into g_part.
//   MODE 0: B accessed as Q_S[k][j]   (Y = X @ Q_S)
//   MODE 1: B accessed as Q_S[j][k]   (Z = W @ Q_S^T), A comes from g_W buf 1
// 128 threads/CTA, each computes an 8(M) x 4(N) register tile. Grid (64, 8).
// ---------------------------------------------------------------------------
template <int MODE>
__global__ void gemm64_kernel(const float* __restrict__ A,
                              const float* __restrict__ B) {
    __shared__ float As[BK][M64 + 4];  // [k][i]
    __shared__ float Bs[BK][NT + 4];   // [k][j]

    const int j0 = blockIdx.x * NT;
    const int k0 = blockIdx.y * KC;
    const int tid = threadIdx.x;       // 128
    const int tx = tid & 15;           // col group -> 4 cols
    const int ty = tid >> 4;           // row group -> 8 rows (0..7)

    const float* Ap = (MODE == 0) ? A : (g_W + WSZ);

    float acc[8][4];
    #pragma unroll
    for (int r = 0; r < 8; r++)
        #pragma unroll
        for (int c = 0; c < 4; c++) acc[r][c] = 0.0f;

    for (int kk = 0; kk < KC; kk += BK) {
        // A tile: 64 x 16 -> As[k][i]
        #pragma unroll
        for (int l = 0; l < 8; l++) {
            int idx = tid + l * 128;
            int i = idx >> 4, k = idx & 15;
            As[k][i] = Ap[i * KK + k0 + kk + k];
        }
        // B tile: 16 x 64 -> Bs[k][j]
        #pragma unroll
        for (int l = 0; l < 8; l++) {
            int idx = tid + l * 128;
            if (MODE == 0) {
                int k = idx >> 6, j = idx & 63;
                Bs[k][j] = B[(size_t)(k0 + kk + k) * NN + j0 + j];
            } else {
                int j = idx >> 4, k = idx & 15;
                Bs[k][j] = B[(size_t)(j0 + j) * KK + k0 + kk + k];
            }
        }
        __syncthreads();

        #pragma unroll
        for (int k = 0; k < BK; k++) {
            float4 a0 = *(float4*)&As[k][ty * 8];
            float4 a1 = *(float4*)&As[k][ty * 8 + 4];
            float4 b  = *(float4*)&Bs[k][tx * 4];
            float av[8] = {a0.x, a0.y, a0.z, a0.w, a1.x, a1.y, a1.z, a1.w};
            float bv[4] = {b.x, b.y, b.z, b.w};
            #pragma unroll
            for (int r = 0; r < 8; r++)
                #pragma unroll
                for (int c = 0; c < 4; c++) acc[r][c] += av[r] * bv[c];
        }
        __syncthreads();
    }

    float* out = g_part + (size_t)blockIdx.y * WSZ;
    #pragma unroll
    for (int r = 0; r < 8; r++) {
        int i = ty * 8 + r;
        float4 v = make_float4(acc[r][0], acc[r][1], acc[r][2], acc[r][3]);
        *(float4*)&out[i * NN + j0 + tx * 4] = v;
    }
}

// ---------------------------------------------------------------------------
// Sum the 8 split-K partials. Writes g_W[0] (use_dout=0) or d_out (use_dout=1).
// ---------------------------------------------------------------------------
__global__ void reduce_kernel(float* __restrict__ dout, int use_dout) {
    int idx = blockIdx.x * blockDim.x + threadIdx.x;  // float4 index, 65536 total
    float4 s = make_float4(0.f, 0.f, 0.f, 0.f);
    #pragma unroll
    for (int p = 0; p < KSPLIT; p++) {
        float4 v = *(const float4*)&g_part[(size_t)p * WSZ + idx * 4];
        s.x += v.x; s.y += v.y; s.z += v.z; s.w += v.w;
    }
    float* out = use_dout ? dout : g_W;
    *(float4*)&out[idx * 4] = s;
}

// ---------------------------------------------------------------------------
// Doubling step t: Wout = Win + diag-col(c_j^(2^t)) * (G^(2^t) @ Win)
// c_j = gamma * Lambda_S[j]. After t = 0..4 this equals sum_{k<32} c^k G^k Y,
// i.e. (I - c_j G)^{-1} y_j to ~1e-18 (spectral radius <= 0.76 * lam_max(G)).
// Grid: 128 CTAs x 32 columns, 256 threads, 4(M) x 2(N) tiles.
// ---------------------------------------------------------------------------
__global__ void solve_step_kernel(const float* __restrict__ Lam,
                                  const float* __restrict__ gamma,
                                  int t) {
    __shared__ float Gs[M64][M64 + 4];
    __shared__ float Ws[M64][32 + 4];

    const float* Win  = g_W + (size_t)(t & 1) * WSZ;
    float*       Wout = g_W + (size_t)((t + 1) & 1) * WSZ;
    const float* Gp   = g_Gpow + (size_t)t * M64 * M64;

    const int j0 = blockIdx.x * 32;
    const int tid = threadIdx.x;  // 256

    #pragma unroll
    for (int l = 0; l < 4; l++) {
        int idx = tid + l * 256;
        int i = idx >> 4, kq = idx & 15;
        *(float4*)&Gs[i][kq * 4] = *(const float4*)&Gp[i * 64 + kq * 4];
    }
    #pragma unroll
    for (int l = 0; l < 8; l++) {
        int idx = tid + l * 256;
        int k = idx >> 5, c = idx & 31;
        Ws[k][c] = Win[k * NN + j0 + c];
    }
    __syncthreads();

    const int ty = tid >> 4;  // rows ty*4 .. +3
    const int tx = tid & 15;  // cols tx*2, tx*2+1

    float acc[4][2];
    #pragma unroll
    for (int r = 0; r < 4; r++) { acc[r][0] = 0.f; acc[r][1] = 0.f; }

    for (int k = 0; k < 64; k++) {
        // (G W)[i][j] = sum_k G[i][k] W[k][j]; Gs[k][i] == G[i][k] (symmetric)
        float4 a = *(float4*)&Gs[k][ty * 4];
        float b0 = Ws[k][tx * 2];
        float b1 = Ws[k][tx * 2 + 1];
        acc[0][0] += a.x * b0;  acc[0][1] += a.x * b1;
        acc[1][0] += a.y * b0;  acc[1][1] += a.y * b1;
        acc[2][0] += a.z * b0;  acc[2][1] += a.z * b1;
        acc[3][0] += a.w * b0;  acc[3][1] += a.w * b1;
    }

    const float gm = gamma[0];
    #pragma unroll
    for (int c = 0; c < 2; c++) {
        int j = j0 + tx * 2 + c;
        float cv = gm * Lam[j];
        float p = cv;
        for (int s = 0; s < t; s++) p *= p;   // p = cv^(2^t)
        #pragma unroll
        for (int r = 0; r < 4; r++) {
            int i = ty * 4 + r;
            Wout[i * NN + j] = Ws[i][tx * 2 + c] + p * acc[r][c];
        }
    }
}

// ---------------------------------------------------------------------------
extern "C" void kernel_launch(void* const* d_in, const int* in_sizes, int n_in,
                              void* d_out, int out_size) {
    const float* X   = (const float*)d_in[0];  // 64 x 4096
    const float* F   = (const float*)d_in[1];  // 64 x 64
    const float* Q   = (const float*)d_in[2];  // 4096 x 4096
    const float* Lam = (const float*)d_in[3];  // 4096
    const float* gam = (const float*)d_in[4];  // scalar
    float* out = (float*)d_out;                // 64 x 4096

    // G and its 2^t powers (independent small chain).
    prep_gpow_kernel<<<1, 256>>>(F);

    // Y = X @ Q_S  (split-K partials, then reduce into g_W[0]).
    gemm64_kernel<0><<<dim3(NN / NT, KSPLIT), 128>>>(X, Q);
    reduce_kernel<<<(WSZ / 4) / 256, 256>>>(nullptr, 0);

    // W = (I - c_j G)^{-1} Y  columnwise via 5 geometric-doubling steps.
    for (int t = 0; t < NSTEPS; t++)
        solve_step_kernel<<<NN / 32, 256>>>(Lam, gam, t);

    // Z = W @ Q_S^T  (W ends in g_W buffer 1), reduce straight into d_out.
    gemm64_kernel<1><<<dim3(NN / NT, KSPLIT), 128>>>(nullptr, Q);
    reduce_kernel<<<(WSZ / 4) / 256, 256>>>(out, 1);
}

// round 16
// speedup vs baseline: 1.8436x; 1.8422x over previous
#include <cuda_runtime.h>
#include <cuda_bf16.h>
#include <cstdint>
#include <math.h>

// Shapes: X (64,4096), F (64,64), Q_S (4096,4096), Lambda_S (4096), gamma.
// Out Z (64,4096) fp32.
#define NN 4096
#define KK 4096
#define NSTEPS 5
#define WSZ (64 * NN)
#define KSPLIT 4
#define KC (KK / KSPLIT)   // 1024
#define BK 32
#define NIT (KC / BK)      // 32

// Static scratch (no allocations anywhere).
__device__ float g_Gpow[NSTEPS * 64 * 64];     // G^(2^t)
__device__ float g_part[KSPLIT * WSZ];         // split-K partials (4 MB)
__device__ __nv_bfloat16 g_Wbf[128 * NN];      // W split: rows 0-63 hi, 64-127 lo

// ---------------------------------------------------------------------------
// Warp-MMA helpers (sm_80-baseline PTX: legal on compute_103 virtual arch).
// ---------------------------------------------------------------------------
__device__ __forceinline__ uint32_t smem_u32(const void* p) {
    uint32_t a;
    asm("{ .reg .u64 t; cvta.to.shared.u64 t, %1; cvt.u32.u64 %0, t; }"
        : "=r"(a) : "l"(p));
    return a;
}
__device__ __forceinline__ void ldsm4(uint32_t* r, uint32_t a) {
    asm volatile("ldmatrix.sync.aligned.m8n8.x4.shared.b16 {%0,%1,%2,%3}, [%4];"
                 : "=r"(r[0]), "=r"(r[1]), "=r"(r[2]), "=r"(r[3]) : "r"(a));
}
__device__ __forceinline__ void ldsm4t(uint32_t* r, uint32_t a) {
    asm volatile("ldmatrix.sync.aligned.m8n8.x4.trans.shared.b16 {%0,%1,%2,%3}, [%4];"
                 : "=r"(r[0]), "=r"(r[1]), "=r"(r[2]), "=r"(r[3]) : "r"(a));
}
__device__ __forceinline__ void mma16816(float* c, const uint32_t* a,
                                         uint32_t b0, uint32_t b1) {
    asm volatile(
        "mma.sync.aligned.m16n8k16.row.col.f32.bf16.bf16.f32 "
        "{%0,%1,%2,%3}, {%4,%5,%6,%7}, {%8,%9}, {%0,%1,%2,%3};"
        : "+f"(c[0]), "+f"(c[1]), "+f"(c[2]), "+f"(c[3])
        : "r"(a[0]), "r"(a[1]), "r"(a[2]), "r"(a[3]), "r"(b0), "r"(b1));
}

__device__ __forceinline__ uint32_t pk(float a, float b) {
    __nv_bfloat162 t = __floats2bfloat162_rn(a, b);
    return *reinterpret_cast<uint32_t*>(&t);
}
// Split (x,y) into bf16 hi pair + bf16 lo pair (hi exact-residual split).
__device__ __forceinline__ void split2(float x, float y, uint32_t& hi, uint32_t& lo) {
    float hx = __bfloat162float(__float2bfloat16(x));
    float hy = __bfloat162float(__float2bfloat16(y));
    hi = pk(hx, hy);
    lo = pk(x - hx, y - hy);
}

// ---------------------------------------------------------------------------
// Prep: G = F^T F / ||F^T F||_F, then G^2, G^4, G^8, G^16 (one CTA, fp32).
// ---------------------------------------------------------------------------
__global__ void prep_gpow_kernel(const float* __restrict__ F) {
    __shared__ float Fs[64][68];
    __shared__ float Gs[64][68];
    __shared__ float rbuf[8];
    __shared__ float sh_scale;

    const int tid = threadIdx.x;  // 256
    const int lane = tid & 31, wid = tid >> 5;

    #pragma unroll
    for (int l = 0; l < 4; l++) {
        int idx = tid + l * 256;
        int i = idx >> 4, kq = idx & 15;
        *(float4*)&Fs[i][kq * 4] = *(const float4*)&F[i * 64 + kq * 4];
    }
    __syncthreads();

    const int ti = (tid >> 4) * 4;
    const int tj = (tid & 15) * 4;

    float acc[4][4];
    #pragma unroll
    for (int r = 0; r < 4; r++)
        #pragma unroll
        for (int c = 0; c < 4; c++) acc[r][c] = 0.0f;

    for (int k = 0; k < 64; k++) {
        float4 a = *(float4*)&Fs[k][ti];
        float4 b = *(float4*)&Fs[k][tj];
        float av[4] = {a.x, a.y, a.z, a.w};
        float bv[4] = {b.x, b.y, b.z, b.w};
        #pragma unroll
        for (int r = 0; r < 4; r++)
            #pragma unroll
            for (int c = 0; c < 4; c++) acc[r][c] += av[r] * bv[c];
    }

    float ss = 0.0f;
    #pragma unroll
    for (int r = 0; r < 4; r++)
        #pragma unroll
        for (int c = 0; c < 4; c++) ss += acc[r][c] * acc[r][c];
    #pragma unroll
    for (int off = 16; off > 0; off >>= 1)
        ss += __shfl_xor_sync(0xffffffffu, ss, off);
    if (lane == 0) rbuf[wid] = ss;
    __syncthreads();
    if (tid == 0) {
        float tot = 0.0f;
        #pragma unroll
        for (int w = 0; w < 8; w++) tot += rbuf[w];
        sh_scale = 1.0f / (sqrtf(tot) + 1e-12f);
    }
    __syncthreads();
    const float scale = sh_scale;

    #pragma unroll
    for (int r = 0; r < 4; r++)
        #pragma unroll
        for (int c = 0; c < 4; c++) {
            float v = acc[r][c] * scale;
            Gs[ti + r][tj + c] = v;
            g_Gpow[(ti + r) * 64 + (tj + c)] = v;
        }
    __syncthreads();

    for (int t = 1; t < NSTEPS; t++) {
        float a2[4][4];
        #pragma unroll
        for (int r = 0; r < 4; r++)
            #pragma unroll
            for (int c = 0; c < 4; c++) a2[r][c] = 0.0f;

        for (int k = 0; k < 64; k++) {
            float4 a = *(float4*)&Gs[k][ti];
            float4 b = *(float4*)&Gs[k][tj];
            float av[4] = {a.x, a.y, a.z, a.w};
            float bv[4] = {b.x, b.y, b.z, b.w};
            #pragma unroll
            for (int r = 0; r < 4; r++)
                #pragma unroll
                for (int c = 0; c < 4; c++) a2[r][c] += av[r] * bv[c];
        }
        __syncthreads();
        #pragma unroll
        for (int r = 0; r < 4; r++)
            #pragma unroll
            for (int c = 0; c < 4; c++) {
                Gs[ti + r][tj + c] = a2[r][c];
                g_Gpow[t * 4096 + (ti + r) * 64 + (tj + c)] = a2[r][c];
            }
        __syncthreads();
    }
}

// ---------------------------------------------------------------------------
// HMMA GEMM, split-K=4. Grid (32 N-tiles of 128, 4 K-splits), 256 threads.
// CTA computes C(64 x 128) partial with 3-term bf16 split:
//     C = Ah*Bh + Ah*Bl + Al*Bh
// A hi rows 0-63 / lo rows 64-127 of the smem A tile.
//   MODE 0: Y = X @ Q      (A = X fp32 -> split inline; B = Q[k][j], trans-LDSM)
//   MODE 1: Z = W @ Q^T    (A = g_Wbf pre-split;        B = Q[j][k], plain LDSM)
// Partials -> g_part[splitK][64][4096].
// ---------------------------------------------------------------------------
// smem: A 128 rows x 40 bf16 (80B padded rows -> conflict-free ldmatrix).
//       B MODE0: hi/lo 32 rows x 136 bf16 (272B rows); MODE1: hi/lo 128 x 40.
template <int MODE>
__global__ void __launch_bounds__(256, 1)
gemm_mma_kernel(const float* __restrict__ Xf, const float* __restrict__ Q) {
    __shared__ __align__(16) char sA[128 * 80];            // 10240 B
    __shared__ __align__(16) char sB[20480];               // MODE0 uses 17408 B

    const int tid = threadIdx.x;
    const int lane = tid & 31, wid = tid >> 5;
    const int wm = wid & 1;        // 2 warp rows (32 M each)
    const int wn = wid >> 1;       // 4 warp cols (32 N each)
    const int j0 = blockIdx.x * 128;
    const int k0 = blockIdx.y * KC;

    const uint32_t sAu = smem_u32(sA), sBu = smem_u32(sB);
    const int strideB = (MODE == 0) ? 272 : 80;            // bytes per B row
    const uint32_t loB = (MODE == 0) ? 8704u : 10240u;     // hi->lo byte offset

    const int lrow = lane & 15;
    const int lcol = (lane >> 4) << 3;                     // 0 or 8

    float C[2][4][4];
    #pragma unroll
    for (int mt = 0; mt < 2; mt++)
        #pragma unroll
        for (int nt = 0; nt < 4; nt++)
            #pragma unroll
            for (int e = 0; e < 4; e++) C[mt][nt][e] = 0.0f;

    float4 aF[2]; uint4 aH[2]; float4 bF[4];

    // ---- LDG stage (into registers) ----
    auto do_ldg = [&](int kb) {
        if (MODE == 0) {
            #pragma unroll
            for (int l = 0; l < 2; l++) {
                int idx = tid + l * 256;
                int m = idx >> 3, c = idx & 7;            // 64 rows x 8 float4
                aF[l] = *(const float4*)&Xf[(size_t)m * KK + kb + c * 4];
            }
        } else {
            #pragma unroll
            for (int l = 0; l < 2; l++) {
                int idx = tid + l * 256;
                int m = idx >> 2, c = idx & 3;            // 128 rows x 4 uint4
                aH[l] = *(const uint4*)&g_Wbf[(size_t)m * KK + kb + c * 8];
            }
        }
        #pragma unroll
        for (int l = 0; l < 4; l++) {
            int idx = tid + l * 256;
            if (MODE == 0) {
                int r = idx >> 5, c = idx & 31;           // 32 k-rows x 32 float4
                bF[l] = *(const float4*)&Q[(size_t)(kb + r) * NN + j0 + c * 4];
            } else {
                int r = idx >> 3, c = idx & 7;            // 128 j-rows x 8 float4
                bF[l] = *(const float4*)&Q[(size_t)(j0 + r) * NN + kb + c * 4];
            }
        }
    };

    // ---- STS stage (bf16 split into padded smem) ----
    auto do_sts = [&]() {
        if (MODE == 0) {
            #pragma unroll
            for (int l = 0; l < 2; l++) {
                int idx = tid + l * 256;
                int m = idx >> 3, c = idx & 7;
                uint32_t h0, l0, h1, l1;
                split2(aF[l].x, aF[l].y, h0, l0);
                split2(aF[l].z, aF[l].w, h1, l1);
                *(uint2*)(sA + m * 80 + c * 8)        = make_uint2(h0, h1);
                *(uint2*)(sA + (m + 64) * 80 + c * 8) = make_uint2(l0, l1);
            }
        } else {
            #pragma unroll
            for (int l = 0; l < 2; l++) {
                int idx = tid + l * 256;
                int m = idx >> 2, c = idx & 3;
                *(uint4*)(sA + m * 80 + c * 16) = aH[l];
            }
        }
        #pragma unroll
        for (int l = 0; l < 4; l++) {
            int idx = tid + l * 256;
            int r, c;
            if (MODE == 0) { r = idx >> 5; c = idx & 31; }
            else           { r = idx >> 3; c = idx & 7; }
            uint32_t h0, l0, h1, l1;
            split2(bF[l].x, bF[l].y, h0, l0);
            split2(bF[l].z, bF[l].w, h1, l1);
            uint32_t off = (uint32_t)(r * strideB + c * 8);
            *(uint2*)(sB + off)       = make_uint2(h0, h1);
            *(uint2*)(sB + loB + off) = make_uint2(l0, l1);
        }
    };

    // ---- compute stage: 2 k16 steps, 48 MMAs ----
    auto do_compute = [&]() {
        #pragma unroll
        for (int s = 0; s < 2; s++) {
            const int kk = s * 16;
            uint32_t ah[2][4], al[2][4], bh[2][4], bl[2][4];
            #pragma unroll
            for (int mt = 0; mt < 2; mt++) {
                uint32_t ab = sAu + (uint32_t)((wm * 32 + mt * 16 + lrow) * 80 +
                                               (kk + lcol) * 2);
                ldsm4(ah[mt], ab);
                ldsm4(al[mt], ab + 64u * 80u);
            }
            #pragma unroll
            for (int ng = 0; ng < 2; ng++) {
                if (MODE == 0) {
                    uint32_t bb = sBu + (uint32_t)((kk + lrow) * 272 +
                                                   (wn * 32 + ng * 16 + lcol) * 2);
                    ldsm4t(bh[ng], bb);
                    ldsm4t(bl[ng], bb + loB);
                } else {
                    uint32_t bb = sBu + (uint32_t)((wn * 32 + ng * 16 + lrow) * 80 +
                                                   (kk + lcol) * 2);
                    ldsm4(bh[ng], bb);
                    ldsm4(bl[ng], bb + loB);
                }
            }
            #pragma unroll
            for (int mt = 0; mt < 2; mt++)
                #pragma unroll
                for (int ng = 0; ng < 2; ng++)
                    #pragma unroll
                    for (int h = 0; h < 2; h++) {
                        int nt = ng * 2 + h;
                        uint32_t b0h, b1h, b0l, b1l;
                        if (MODE == 0) {
                            b0h = bh[ng][2 * h]; b1h = bh[ng][2 * h + 1];
                            b0l = bl[ng][2 * h]; b1l = bl[ng][2 * h + 1];
                        } else {
                            b0h = bh[ng][h]; b1h = bh[ng][h + 2];
                            b0l = bl[ng][h]; b1l = bl[ng][h + 2];
                        }
                        mma16816(C[mt][nt], ah[mt], b0h, b1h);   // Ah*Bh
                        mma16816(C[mt][nt], ah[mt], b0l, b1l);   // Ah*Bl
                        mma16816(C[mt][nt], al[mt], b0h, b1h);   // Al*Bh
                    }
        }
    };

    // ---- pipelined mainloop ----
    do_ldg(k0);
    do_sts();
    __syncthreads();
    for (int it = 0; it < NIT; it++) {
        if (it + 1 < NIT) do_ldg(k0 + (it + 1) * BK);
        do_compute();
        __syncthreads();
        if (it + 1 < NIT) {
            do_sts();
            __syncthreads();
        }
    }

    // ---- epilogue: C fragments -> g_part[split] ----
    float* outp = g_part + (size_t)blockIdx.y * WSZ;
    #pragma unroll
    for (int mt = 0; mt < 2; mt++)
        #pragma unroll
        for (int nt = 0; nt < 4; nt++) {
            int m = wm * 32 + mt * 16 + (lane >> 2);
            int j = j0 + wn * 32 + nt * 8 + 2 * (lane & 3);
            *(float2*)&outp[(size_t)m * NN + j] =
                make_float2(C[mt][nt][0], C[mt][nt][1]);
            *(float2*)&outp[(size_t)(m + 8) * NN + j] =
                make_float2(C[mt][nt][2], C[mt][nt][3]);
        }
}

// ---------------------------------------------------------------------------
// Fused solver: Y = sum of 4 partials; 5 doubling steps W += c^(2^t) G^(2^t) W;
// emit W as bf16 hi/lo stacked into g_Wbf. 128 CTAs x 32 cols, 256 threads.
// ---------------------------------------------------------------------------
__global__ void __launch_bounds__(256, 1)
solve_fused_kernel(const float* __restrict__ Lam, const float* __restrict__ gamma) {
    __shared__ float Gs[64][68];
    __shared__ float Ws[2][64][33];

    const int tid = threadIdx.x;
    const int j0 = blockIdx.x * 32;

    #pragma unroll
    for (int l = 0; l < 8; l++) {
        int idx = tid + l * 256;
        int m = idx >> 5, c = idx & 31;
        size_t o = (size_t)m * NN + j0 + c;
        Ws[0][m][c] = g_part[o] + g_part[WSZ + o] +
                      g_part[2 * (size_t)WSZ + o] + g_part[3 * (size_t)WSZ + o];
    }

    const int ty = tid >> 4;   // 4 rows: ty*4..+3
    const int tx = tid & 15;   // 2 cols
    const float gm = gamma[0];
    float p0 = gm * Lam[j0 + tx * 2];
    float p1 = gm * Lam[j0 + tx * 2 + 1];
    int cur = 0;

    for (int t = 0; t < NSTEPS; t++) {
        __syncthreads();
        #pragma unroll
        for (int l = 0; l < 4; l++) {
            int idx = tid + l * 256;
            int i = idx >> 4, c4 = idx & 15;
            *(float4*)&Gs[i][c4 * 4] = *(const float4*)&g_Gpow[t * 4096 + i * 64 + c4 * 4];
        }
        __syncthreads();

        float acc[4][2];
        #pragma unroll
        for (int r = 0; r < 4; r++) { acc[r][0] = 0.f; acc[r][1] = 0.f; }

        for (int k = 0; k < 64; k++) {
            float4 a = *(float4*)&Gs[k][ty * 4];  // G symmetric
            float b0 = Ws[cur][k][tx * 2];
            float b1 = Ws[cur][k][tx * 2 + 1];
            acc[0][0] += a.x * b0;  acc[0][1] += a.x * b1;
            acc[1][0] += a.y * b0;  acc[1][1] += a.y * b1;
            acc[2][0] += a.z * b0;  acc[2][1] += a.z * b1;
            acc[3][0] += a.w * b0;  acc[3][1] += a.w * b1;
        }
        #pragma unroll
        for (int r = 0; r < 4; r++) {
            int i = ty * 4 + r;
            Ws[cur ^ 1][i][tx * 2]     = Ws[cur][i][tx * 2]     + p0 * acc[r][0];
            Ws[cur ^ 1][i][tx * 2 + 1] = Ws[cur][i][tx * 2 + 1] + p1 * acc[r][1];
        }
        cur ^= 1;
        p0 *= p0;
        p1 *= p1;
    }

    #pragma unroll
    for (int r = 0; r < 4; r++) {
        int i = ty * 4 + r;
        #pragma unroll
        for (int c = 0; c < 2; c++) {
            int j = j0 + tx * 2 + c;
            float w = Ws[cur][i][tx * 2 + c];
            __nv_bfloat16 h = __float2bfloat16(w);
            float lo = w - __bfloat162float(h);
            g_Wbf[(size_t)i * NN + j] = h;
            g_Wbf[(size_t)(i + 64) * NN + j] = __float2bfloat16(lo);
        }
    }
}

// ---------------------------------------------------------------------------
// Final reduce: out = sum of 4 partials (64 x 4096).
// ---------------------------------------------------------------------------
__global__ void reduce4_kernel(float* __restrict__ out) {
    int idx = blockIdx.x * 256 + threadIdx.x;  // float4 units, 65536 total
    float4 a = ((const float4*)g_part)[idx];
    float4 b = ((const float4*)g_part)[idx + WSZ / 4];
    float4 c = ((const float4*)g_part)[idx + 2 * (WSZ / 4)];
    float4 d = ((const float4*)g_part)[idx + 3 * (WSZ / 4)];
    a.x += b.x + c.x + d.x;
    a.y += b.y + c.y + d.y;
    a.z += b.z + c.z + d.z;
    a.w += b.w + c.w + d.w;
    ((float4*)out)[idx] = a;
}

// ---------------------------------------------------------------------------
extern "C" void kernel_launch(void* const* d_in, const int* in_sizes, int n_in,
                              void* d_out, int out_size) {
    const float* X   = (const float*)d_in[0];
    const float* F   = (const float*)d_in[1];
    const float* Q   = (const float*)d_in[2];
    const float* Lam = (const float*)d_in[3];
    const float* gam = (const float*)d_in[4];
    float* out = (float*)d_out;

    prep_gpow_kernel<<<1, 256>>>(F);
    gemm_mma_kernel<0><<<dim3(NN / 128, KSPLIT), 256>>>(X, Q);
    solve_fused_kernel<<<NN / 32, 256>>>(Lam, gam);
    gemm_mma_kernel<1><<<dim3(NN / 128, KSPLIT), 256>>>(nullptr, Q);
    reduce4_kernel<<<WSZ / 4 / 256, 256>>>(out);
}

// round 17
// speedup vs baseline: 1.9752x; 1.0714x over previous
#include <cuda_runtime.h>
#include <cuda_bf16.h>
#include <cstdint>
#include <math.h>

// Shapes: X (64,4096), F (64,64), Q_S (4096,4096), Lambda_S (4096), gamma.
// Out Z (64,4096) fp32.
#define NN 4096
#define KK 4096
#define NSTEPS 5
#define WSZ (64 * NN)
#define KSPLIT 8
#define KC (KK / KSPLIT)   // 512
#define BK 32
#define NIT (KC / BK)      // 16

// Static scratch (no allocations anywhere).
__device__ float g_Gpow[NSTEPS * 64 * 64];     // G^(2^t)
__device__ float g_part[KSPLIT * WSZ];         // split-K partials (8 MB)
__device__ __nv_bfloat16 g_Wbf[128 * NN];      // W split: rows 0-63 hi, 64-127 lo

// ---------------------------------------------------------------------------
// Warp-MMA helpers (sm_80-baseline PTX: legal on compute_103 virtual arch).
// ---------------------------------------------------------------------------
__device__ __forceinline__ uint32_t smem_u32(const void* p) {
    uint32_t a;
    asm("{ .reg .u64 t; cvta.to.shared.u64 t, %1; cvt.u32.u64 %0, t; }"
        : "=r"(a) : "l"(p));
    return a;
}
__device__ __forceinline__ void ldsm4(uint32_t* r, uint32_t a) {
    asm volatile("ldmatrix.sync.aligned.m8n8.x4.shared.b16 {%0,%1,%2,%3}, [%4];"
                 : "=r"(r[0]), "=r"(r[1]), "=r"(r[2]), "=r"(r[3]) : "r"(a));
}
__device__ __forceinline__ void ldsm4t(uint32_t* r, uint32_t a) {
    asm volatile("ldmatrix.sync.aligned.m8n8.x4.trans.shared.b16 {%0,%1,%2,%3}, [%4];"
                 : "=r"(r[0]), "=r"(r[1]), "=r"(r[2]), "=r"(r[3]) : "r"(a));
}
__device__ __forceinline__ void mma16816(float* c, const uint32_t* a,
                                         uint32_t b0, uint32_t b1) {
    asm volatile(
        "mma.sync.aligned.m16n8k16.row.col.f32.bf16.bf16.f32 "
        "{%0,%1,%2,%3}, {%4,%5,%6,%7}, {%8,%9}, {%0,%1,%2,%3};"
        : "+f"(c[0]), "+f"(c[1]), "+f"(c[2]), "+f"(c[3])
        : "r"(a[0]), "r"(a[1]), "r"(a[2]), "r"(a[3]), "r"(b0), "r"(b1));
}

__device__ __forceinline__ uint32_t pk(float a, float b) {
    __nv_bfloat162 t = __floats2bfloat162_rn(a, b);
    return *reinterpret_cast<uint32_t*>(&t);
}
// Split (x,y) into bf16 hi pair + bf16 lo pair (hi exact-residual split).
__device__ __forceinline__ void split2(float x, float y, uint32_t& hi, uint32_t& lo) {
    float hx = __bfloat162float(__float2bfloat16(x));
    float hy = __bfloat162float(__float2bfloat16(y));
    hi = pk(hx, hy);
    lo = pk(x - hx, y - hy);
}

// ---------------------------------------------------------------------------
// Prep: G = F^T F / ||F^T F||_F, then G^2, G^4, G^8, G^16 (one CTA, fp32).
// ---------------------------------------------------------------------------
__global__ void prep_gpow_kernel(const float* __restrict__ F) {
    __shared__ float Fs[64][68];
    __shared__ float Gs[64][68];
    __shared__ float rbuf[8];
    __shared__ float sh_scale;

    const int tid = threadIdx.x;  // 256
    const int lane = tid & 31, wid = tid >> 5;

    #pragma unroll
    for (int l = 0; l < 4; l++) {
        int idx = tid + l * 256;
        int i = idx >> 4, kq = idx & 15;
        *(float4*)&Fs[i][kq * 4] = *(const float4*)&F[i * 64 + kq * 4];
    }
    __syncthreads();

    const int ti = (tid >> 4) * 4;
    const int tj = (tid & 15) * 4;

    float acc[4][4];
    #pragma unroll
    for (int r = 0; r < 4; r++)
        #pragma unroll
        for (int c = 0; c < 4; c++) acc[r][c] = 0.0f;

    for (int k = 0; k < 64; k++) {
        float4 a = *(float4*)&Fs[k][ti];
        float4 b = *(float4*)&Fs[k][tj];
        float av[4] = {a.x, a.y, a.z, a.w};
        float bv[4] = {b.x, b.y, b.z, b.w};
        #pragma unroll
        for (int r = 0; r < 4; r++)
            #pragma unroll
            for (int c = 0; c < 4; c++) acc[r][c] += av[r] * bv[c];
    }

    float ss = 0.0f;
    #pragma unroll
    for (int r = 0; r < 4; r++)
        #pragma unroll
        for (int c = 0; c < 4; c++) ss += acc[r][c] * acc[r][c];
    #pragma unroll
    for (int off = 16; off > 0; off >>= 1)
        ss += __shfl_xor_sync(0xffffffffu, ss, off);
    if (lane == 0) rbuf[wid] = ss;
    __syncthreads();
    if (tid == 0) {
        float tot = 0.0f;
        #pragma unroll
        for (int w = 0; w < 8; w++) tot += rbuf[w];
        sh_scale = 1.0f / (sqrtf(tot) + 1e-12f);
    }
    __syncthreads();
    const float scale = sh_scale;

    #pragma unroll
    for (int r = 0; r < 4; r++)
        #pragma unroll
        for (int c = 0; c < 4; c++) {
            float v = acc[r][c] * scale;
            Gs[ti + r][tj + c] = v;
            g_Gpow[(ti + r) * 64 + (tj + c)] = v;
        }
    __syncthreads();

    for (int t = 1; t < NSTEPS; t++) {
        float a2[4][4];
        #pragma unroll
        for (int r = 0; r < 4; r++)
            #pragma unroll
            for (int c = 0; c < 4; c++) a2[r][c] = 0.0f;

        for (int k = 0; k < 64; k++) {
            float4 a = *(float4*)&Gs[k][ti];
            float4 b = *(float4*)&Gs[k][tj];
            float av[4] = {a.x, a.y, a.z, a.w};
            float bv[4] = {b.x, b.y, b.z, b.w};
            #pragma unroll
            for (int r = 0; r < 4; r++)
                #pragma unroll
                for (int c = 0; c < 4; c++) a2[r][c] += av[r] * bv[c];
        }
        __syncthreads();
        #pragma unroll
        for (int r = 0; r < 4; r++)
            #pragma unroll
            for (int c = 0; c < 4; c++) {
                Gs[ti + r][tj + c] = a2[r][c];
                g_Gpow[t * 4096 + (ti + r) * 64 + (tj + c)] = a2[r][c];
            }
        __syncthreads();
    }
}

// ---------------------------------------------------------------------------
// HMMA GEMM, split-K=8. Grid (32 N-tiles of 128, 8 K-splits), 256 threads,
// 2 CTAs/SM. CTA computes C(64 x 128) partial with 3-term bf16 split:
//     C = Ah*Bh + Ah*Bl + Al*Bh
//   MODE 0: Y = X @ Q      (A = X fp32 -> split inline; B = Q[k][j], trans-LDSM)
//   MODE 1: Z = W @ Q^T    (A = g_Wbf pre-split;        B = Q[j][k], plain LDSM)
// Double-buffered smem, ONE barrier per mainloop iteration.
// ---------------------------------------------------------------------------
// Dynamic smem layout: A buf0/buf1 (10240 B each, 80 B rows),
// then B buf0/buf1 (MODE0: 17408 B each, 272 B rows; MODE1: 20480 B, 80 B rows).
#define ABUF 10240
#define SMEM_MAX 61440

template <int MODE>
__global__ void __launch_bounds__(256, 2)
gemm_mma_kernel(const float* __restrict__ Xf, const float* __restrict__ Q) {
    extern __shared__ __align__(16) char smem[];
    const int BSEG = (MODE == 0) ? 17408 : 20480;
    char* sA[2] = {smem, smem + ABUF};
    char* sB[2] = {smem + 2 * ABUF, smem + 2 * ABUF + BSEG};

    const int tid = threadIdx.x;
    const int lane = tid & 31, wid = tid >> 5;
    const int wm = wid & 1;        // 2 warp rows (32 M each)
    const int wn = wid >> 1;       // 4 warp cols (32 N each)
    const int j0 = blockIdx.x * 128;
    const int k0 = blockIdx.y * KC;

    const int strideB = (MODE == 0) ? 272 : 80;            // bytes per B row
    const uint32_t loB = (MODE == 0) ? 8704u : 10240u;     // hi->lo byte offset

    const int lrow = lane & 15;
    const int lcol = (lane >> 4) << 3;                     // 0 or 8

    float C[2][4][4];
    #pragma unroll
    for (int mt = 0; mt < 2; mt++)
        #pragma unroll
        for (int nt = 0; nt < 4; nt++)
            #pragma unroll
            for (int e = 0; e < 4; e++) C[mt][nt][e] = 0.0f;

    float4 aF[2]; uint4 aH[2]; float4 bF[4];

    // ---- LDG stage (into registers) ----
    auto do_ldg = [&](int kb) {
        if (MODE == 0) {
            #pragma unroll
            for (int l = 0; l < 2; l++) {
                int idx = tid + l * 256;
                int m = idx >> 3, c = idx & 7;            // 64 rows x 8 float4
                aF[l] = *(const float4*)&Xf[(size_t)m * KK + kb + c * 4];
            }
        } else {
            #pragma unroll
            for (int l = 0; l < 2; l++) {
                int idx = tid + l * 256;
                int m = idx >> 2, c = idx & 3;            // 128 rows x 4 uint4
                aH[l] = *(const uint4*)&g_Wbf[(size_t)m * KK + kb + c * 8];
            }
        }
        #pragma unroll
        for (int l = 0; l < 4; l++) {
            int idx = tid + l * 256;
            if (MODE == 0) {
                int r = idx >> 5, c = idx & 31;           // 32 k-rows x 32 float4
                bF[l] = *(const float4*)&Q[(size_t)(kb + r) * NN + j0 + c * 4];
            } else {
                int r = idx >> 3, c = idx & 7;            // 128 j-rows x 8 float4
                bF[l] = *(const float4*)&Q[(size_t)(j0 + r) * NN + kb + c * 4];
            }
        }
    };

    // ---- STS stage (bf16 split into padded smem) ----
    auto do_sts = [&](char* Ab, char* Bb) {
        if (MODE == 0) {
            #pragma unroll
            for (int l = 0; l < 2; l++) {
                int idx = tid + l * 256;
                int m = idx >> 3, c = idx & 7;
                uint32_t h0, l0, h1, l1;
                split2(aF[l].x, aF[l].y, h0, l0);
                split2(aF[l].z, aF[l].w, h1, l1);
                *(uint2*)(Ab + m * 80 + c * 8)        = make_uint2(h0, h1);
                *(uint2*)(Ab + (m + 64) * 80 + c * 8) = make_uint2(l0, l1);
            }
        } else {
            #pragma unroll
            for (int l = 0; l < 2; l++) {
                int idx = tid + l * 256;
                int m = idx >> 2, c = idx & 3;
                *(uint4*)(Ab + m * 80 + c * 16) = aH[l];
            }
        }
        #pragma unroll
        for (int l = 0; l < 4; l++) {
            int idx = tid + l * 256;
            int r, c;
            if (MODE == 0) { r = idx >> 5; c = idx & 31; }
            else           { r = idx >> 3; c = idx & 7; }
            uint32_t h0, l0, h1, l1;
            split2(bF[l].x, bF[l].y, h0, l0);
            split2(bF[l].z, bF[l].w, h1, l1);
            uint32_t off = (uint32_t)(r * strideB + c * 8);
            *(uint2*)(Bb + off)       = make_uint2(h0, h1);
            *(uint2*)(Bb + loB + off) = make_uint2(l0, l1);
        }
    };

    // ---- compute stage: 2 k16 steps, 96 MMAs ----
    auto do_compute = [&](uint32_t sAu, uint32_t sBu) {
        #pragma unroll
        for (int s = 0; s < 2; s++) {
            const int kk = s * 16;
            uint32_t ah[2][4], al[2][4], bh[2][4], bl[2][4];
            #pragma unroll
            for (int mt = 0; mt < 2; mt++) {
                uint32_t ab = sAu + (uint32_t)((wm * 32 + mt * 16 + lrow) * 80 +
                                               (kk + lcol) * 2);
                ldsm4(ah[mt], ab);
                ldsm4(al[mt], ab + 64u * 80u);
            }
            #pragma unroll
            for (int ng = 0; ng < 2; ng++) {
                if (MODE == 0) {
                    uint32_t bb = sBu + (uint32_t)((kk + lrow) * 272 +
                                                   (wn * 32 + ng * 16 + lcol) * 2);
                    ldsm4t(bh[ng], bb);
                    ldsm4t(bl[ng], bb + loB);
                } else {
                    uint32_t bb = sBu + (uint32_t)((wn * 32 + ng * 16 + lrow) * 80 +
                                                   (kk + lcol) * 2);
                    ldsm4(bh[ng], bb);
                    ldsm4(bl[ng], bb + loB);
                }
            }
            #pragma unroll
            for (int mt = 0; mt < 2; mt++)
                #pragma unroll
                for (int ng = 0; ng < 2; ng++)
                    #pragma unroll
                    for (int h = 0; h < 2; h++) {
                        int nt = ng * 2 + h;
                        uint32_t b0h, b1h, b0l, b1l;
                        if (MODE == 0) {
                            b0h = bh[ng][2 * h]; b1h = bh[ng][2 * h + 1];
                            b0l = bl[ng][2 * h]; b1l = bl[ng][2 * h + 1];
                        } else {
                            b0h = bh[ng][h]; b1h = bh[ng][h + 2];
                            b0l = bl[ng][h]; b1l = bl[ng][h + 2];
                        }
                        mma16816(C[mt][nt], ah[mt], b0h, b1h);   // Ah*Bh
                        mma16816(C[mt][nt], ah[mt], b0l, b1l);   // Ah*Bl
                        mma16816(C[mt][nt], al[mt], b0h, b1h);   // Al*Bh
                    }
        }
    };

    const uint32_t Au[2] = {smem_u32(sA[0]), smem_u32(sA[1])};
    const uint32_t Bu[2] = {smem_u32(sB[0]), smem_u32(sB[1])};

    // ---- double-buffered mainloop: ONE barrier per iteration ----
    do_ldg(k0);
    do_sts(sA[0], sB[0]);
    __syncthreads();
    for (int it = 0; it < NIT; it++) {
        const int cur = it & 1;
        if (it + 1 < NIT) do_ldg(k0 + (it + 1) * BK);
        do_compute(Au[cur], Bu[cur]);
        if (it + 1 < NIT) do_sts(sA[cur ^ 1], sB[cur ^ 1]);
        __syncthreads();
    }

    // ---- epilogue: C fragments -> g_part[split] ----
    float* outp = g_part + (size_t)blockIdx.y * WSZ;
    #pragma unroll
    for (int mt = 0; mt < 2; mt++)
        #pragma unroll
        for (int nt = 0; nt < 4; nt++) {
            int m = wm * 32 + mt * 16 + (lane >> 2);
            int j = j0 + wn * 32 + nt * 8 + 2 * (lane & 3);
            *(float2*)&outp[(size_t)m * NN + j] =
                make_float2(C[mt][nt][0], C[mt][nt][1]);
            *(float2*)&outp[(size_t)(m + 8) * NN + j] =
                make_float2(C[mt][nt][2], C[mt][nt][3]);
        }
}

// ---------------------------------------------------------------------------
// Fused solver: Y = sum of 8 partials; 5 doubling steps W += c^(2^t) G^(2^t) W;
// emit W as bf16 hi/lo stacked into g_Wbf. 128 CTAs x 32 cols, 256 threads.
// ---------------------------------------------------------------------------
__global__ void __launch_bounds__(256, 1)
solve_fused_kernel(const float* __restrict__ Lam, const float* __restrict__ gamma) {
    __shared__ float Gs[64][68];
    __shared__ float Ws[2][64][33];

    const int tid = threadIdx.x;
    const int j0 = blockIdx.x * 32;

    #pragma unroll
    for (int l = 0; l < 8; l++) {
        int idx = tid + l * 256;
        int m = idx >> 5, c = idx & 31;
        size_t o = (size_t)m * NN + j0 + c;
        float s = 0.0f;
        #pragma unroll
        for (int p = 0; p < KSPLIT; p++) s += g_part[(size_t)p * WSZ + o];
        Ws[0][m][c] = s;
    }

    const int ty = tid >> 4;   // 4 rows: ty*4..+3
    const int tx = tid & 15;   // 2 cols
    const float gm = gamma[0];
    float p0 = gm * Lam[j0 + tx * 2];
    float p1 = gm * Lam[j0 + tx * 2 + 1];
    int cur = 0;

    for (int t = 0; t < NSTEPS; t++) {
        __syncthreads();
        #pragma unroll
        for (int l = 0; l < 4; l++) {
            int idx = tid + l * 256;
            int i = idx >> 4, c4 = idx & 15;
            *(float4*)&Gs[i][c4 * 4] = *(const float4*)&g_Gpow[t * 4096 + i * 64 + c4 * 4];
        }
        __syncthreads();

        float acc[4][2];
        #pragma unroll
        for (int r = 0; r < 4; r++) { acc[r][0] = 0.f; acc[r][1] = 0.f; }

        for (int k = 0; k < 64; k++) {
            float4 a = *(float4*)&Gs[k][ty * 4];  // G symmetric
            float b0 = Ws[cur][k][tx * 2];
            float b1 = Ws[cur][k][tx * 2 + 1];
            acc[0][0] += a.x * b0;  acc[0][1] += a.x * b1;
            acc[1][0] += a.y * b0;  acc[1][1] += a.y * b1;
            acc[2][0] += a.z * b0;  acc[2][1] += a.z * b1;
            acc[3][0] += a.w * b0;  acc[3][1] += a.w * b1;
        }
        #pragma unroll
        for (int r = 0; r < 4; r++) {
            int i = ty * 4 + r;
            Ws[cur ^ 1][i][tx * 2]     = Ws[cur][i][tx * 2]     + p0 * acc[r][0];
            Ws[cur ^ 1][i][tx * 2 + 1] = Ws[cur][i][tx * 2 + 1] + p1 * acc[r][1];
        }
        cur ^= 1;
        p0 *= p0;
        p1 *= p1;
    }

    #pragma unroll
    for (int r = 0; r < 4; r++) {
        int i = ty * 4 + r;
        #pragma unroll
        for (int c = 0; c < 2; c++) {
            int j = j0 + tx * 2 + c;
            float w = Ws[cur][i][tx * 2 + c];
            __nv_bfloat16 h = __float2bfloat16(w);
            float lo = w - __bfloat162float(h);
            g_Wbf[(size_t)i * NN + j] = h;
            g_Wbf[(size_t)(i + 64) * NN + j] = __float2bfloat16(lo);
        }
    }
}

// ---------------------------------------------------------------------------
// Final reduce: out = sum of 8 partials (64 x 4096).
// ---------------------------------------------------------------------------
__global__ void reduce8_kernel(float* __restrict__ out) {
    int idx = blockIdx.x * 256 + threadIdx.x;  // float4 units, 65536 total
    float4 a = ((const float4*)g_part)[idx];
    #pragma unroll
    for (int p = 1; p < KSPLIT; p++) {
        float4 b = ((const float4*)g_part)[idx + p * (WSZ / 4)];
        a.x += b.x; a.y += b.y; a.z += b.z; a.w += b.w;
    }
    ((float4*)out)[idx] = a;
}

// ---------------------------------------------------------------------------
extern "C" void kernel_launch(void* const* d_in, const int* in_sizes, int n_in,
                              void* d_out, int out_size) {
    const float* X   = (const float*)d_in[0];
    const float* F   = (const float*)d_in[1];
    const float* Q   = (const float*)d_in[2];
    const float* Lam = (const float*)d_in[3];
    const float* gam = (const float*)d_in[4];
    float* out = (float*)d_out;

    cudaFuncSetAttribute(gemm_mma_kernel<0>,
                         cudaFuncAttributeMaxDynamicSharedMemorySize, SMEM_MAX);
    cudaFuncSetAttribute(gemm_mma_kernel<1>,
                         cudaFuncAttributeMaxDynamicSharedMemorySize, SMEM_MAX);

    prep_gpow_kernel<<<1, 256>>>(F);
    gemm_mma_kernel<0><<<dim3(NN / 128, KSPLIT), 256, 2 * ABUF + 2 * 17408>>>(X, Q);
    solve_fused_kernel<<<NN / 32, 256>>>(Lam, gam);
    gemm_mma_kernel<1><<<dim3(NN / 128, KSPLIT), 256, 2 * ABUF + 2 * 20480>>>(nullptr, Q);
    reduce8_kernel<<<WSZ / 4 / 256, 256>>>(out);
}